// round 1
// baseline (speedup 1.0000x reference)
#include <cuda_runtime.h>
#include <math.h>

#define K_   19
#define P_   5
#define KP   95
#define D_   64
#define NPIX 32768
#define B_   8
#define TPB  256

// Precomputed per-component params (written by prep_kernel, read by main_kernel)
__device__ float g_w [KP * D_];   // mu_n * inv_sigma2
__device__ float g_i2[KP * D_];   // inv_sigma2
__device__ float g_cc[KP];        // -0.5*sum(mu_n^2*inv2) - sum(log s) - 0.5*D*log(2pi)

// ---------------------------------------------------------------------------
// Prep: l2-normalize means, build w / inv2 / cc.  95 blocks x 64 threads.
// ---------------------------------------------------------------------------
__global__ void prep_kernel(const float* __restrict__ means,
                            const float* __restrict__ diag) {
    int j = blockIdx.x;      // component 0..94  (j = k*P + p)
    int d = threadIdx.x;     // 0..63
    __shared__ float r1[2], r2[2];

    float mu = means[j * D_ + d];
    float s  = diag [j * D_ + d];

    float v = mu * mu;
    #pragma unroll
    for (int o = 16; o; o >>= 1) v += __shfl_xor_sync(0xffffffffu, v, o);
    if ((d & 31) == 0) r1[d >> 5] = v;
    __syncthreads();

    float nrm = sqrtf(r1[0] + r1[1]);
    float mun = mu / fmaxf(nrm, 1e-12f);
    float i2  = 1.0f / (s * s);

    g_w [j * D_ + d] = mun * i2;
    g_i2[j * D_ + d] = i2;

    float c = -0.5f * mun * mun * i2 - logf(s);
    #pragma unroll
    for (int o = 16; o; o >>= 1) c += __shfl_xor_sync(0xffffffffu, c, o);
    if ((d & 31) == 0) r2[d >> 5] = c;
    __syncthreads();

    if (d == 0)
        g_cc[j] = r2[0] + r2[1] - 0.5f * (float)D_ * logf(6.283185307179586f);
}

// ---------------------------------------------------------------------------
// Packed f32x2 helpers (FFMA2 path — PTX-only, per B300 SASS quickref)
// ---------------------------------------------------------------------------
__device__ __forceinline__ unsigned long long ffma2(unsigned long long a,
                                                    unsigned long long b,
                                                    unsigned long long c) {
    unsigned long long d;
    asm("fma.rn.f32x2 %0, %1, %2, %3;" : "=l"(d) : "l"(a), "l"(b), "l"(c));
    return d;
}
__device__ __forceinline__ unsigned long long pk2(float lo, float hi) {
    unsigned long long r;
    asm("mov.b64 %0, {%1, %2};" : "=l"(r) : "f"(lo), "f"(hi));
    return r;
}
__device__ __forceinline__ float hadd2(unsigned long long v) {
    float a, b;
    asm("mov.b64 {%0, %1}, %2;" : "=f"(a), "=f"(b) : "l"(v));
    return a + b;
}

// ---------------------------------------------------------------------------
// Main: one thread per pixel-row.  LN -> L2 -> 95 logprobs -> max5 -> LN(19)
// ---------------------------------------------------------------------------
__global__ void __launch_bounds__(TPB, 1)
main_kernel(const float* __restrict__ bf,
            const float* __restrict__ fw, const float* __restrict__ fb,
            const float* __restrict__ mw, const float* __restrict__ mb,
            float* __restrict__ out) {
    extern __shared__ float smem[];
    float* wsm = smem;                 // KP*D_   (24320 B)
    float* ism = wsm + KP * D_;        // KP*D_   (24320 B)
    float* ccs = ism + KP * D_;        // 96
    float* mws = ccs + 96;             // 20
    float* mbs = mws + 20;             // 20
    float* fws = mbs + 20;             // 64
    float* fbs = fws + 64;             // 64
    float* msm = fbs + 64;             // K_*TPB  (19456 B)

    const int tid = threadIdx.x;

    for (int i = tid; i < KP * D_; i += TPB) { wsm[i] = g_w[i]; ism[i] = g_i2[i]; }
    if (tid < KP) ccs[tid] = g_cc[tid];
    if (tid < K_) { mws[tid] = mw[tid]; mbs[tid] = mb[tid]; }
    if (tid < D_) { fws[tid] = fw[tid]; fbs[tid] = fb[tid]; }
    __syncthreads();

    const int n = blockIdx.x * TPB + tid;
    const int b = blockIdx.y;
    const float* xp = bf + ((size_t)b * D_) * NPIX + n;

    // ---- load row (coalesced: consecutive tid -> consecutive n) ----
    float x[D_];
    #pragma unroll
    for (int d = 0; d < D_; d++) x[d] = xp[(size_t)d * NPIX];

    // ---- layernorm over D ----
    float sm_ = 0.f;
    #pragma unroll
    for (int d = 0; d < D_; d++) sm_ += x[d];
    float mean = sm_ * (1.0f / D_);
    float vs = 0.f;
    #pragma unroll
    for (int d = 0; d < D_; d++) { x[d] -= mean; vs += x[d] * x[d]; }
    float rstd = rsqrtf(vs * (1.0f / D_) + 1e-5f);
    float ss = 0.f;
    #pragma unroll
    for (int d = 0; d < D_; d++) { x[d] = x[d] * rstd * fws[d] + fbs[d]; ss += x[d] * x[d]; }
    // ---- l2 normalize ----
    float rl = 1.0f / fmaxf(sqrtf(ss), 1e-12f);

    // ---- pack x and x^2 into f32x2 registers ----
    unsigned long long x2[D_ / 2], q2[D_ / 2];
    #pragma unroll
    for (int i = 0; i < D_ / 2; i++) {
        float a = x[2 * i] * rl, c = x[2 * i + 1] * rl;
        x2[i] = pk2(a, c);
        q2[i] = pk2(a * a, c * c);
    }

    // ---- 95 components: logp = s1 - 0.5*s2 + cc ; running max per group of 5 ----
    const double2* wd = (const double2*)wsm;
    const double2* id = (const double2*)ism;
    int j = 0;
    for (int k = 0; k < K_; k++) {
        float mk = -3.4e38f;
        #pragma unroll
        for (int p = 0; p < P_; p++, j++) {
            const double2* wr = wd + j * (D_ / 4);
            const double2* ir = id + j * (D_ / 4);
            unsigned long long a0 = 0ull, a1 = 0ull, b0 = 0ull, b1 = 0ull;
            #pragma unroll
            for (int i = 0; i < D_ / 4; i++) {
                double2 wv = wr[i];
                double2 iv = ir[i];
                a0 = ffma2(x2[2 * i    ], __double_as_longlong(wv.x), a0);
                a1 = ffma2(x2[2 * i + 1], __double_as_longlong(wv.y), a1);
                b0 = ffma2(q2[2 * i    ], __double_as_longlong(iv.x), b0);
                b1 = ffma2(q2[2 * i + 1], __double_as_longlong(iv.y), b1);
            }
            float s1 = hadd2(a0) + hadd2(a1);
            float s2 = hadd2(b0) + hadd2(b1);
            float lp = fmaf(-0.5f, s2, s1) + ccs[j];
            mk = fmaxf(mk, lp);
        }
        msm[k * TPB + tid] = mk;   // stride-TPB: conflict-free
    }

    // ---- layernorm over K=19 + transposed store ----
    float s = 0.f;
    #pragma unroll
    for (int k = 0; k < K_; k++) s += msm[k * TPB + tid];
    float m2 = s * (1.0f / K_);
    float v2 = 0.f;
    #pragma unroll
    for (int k = 0; k < K_; k++) { float t = msm[k * TPB + tid] - m2; v2 += t * t; }
    float r2 = rsqrtf(v2 * (1.0f / K_) + 1e-5f);

    float* op = out + ((size_t)b * K_) * NPIX + n;
    #pragma unroll
    for (int k = 0; k < K_; k++)
        op[(size_t)k * NPIX] = (msm[k * TPB + tid] - m2) * r2 * mws[k] + mbs[k];
}

// ---------------------------------------------------------------------------
// Launch
// ---------------------------------------------------------------------------
static const int SMEM_BYTES = (KP * D_ * 2 + 96 + 20 + 20 + 64 + 64 + K_ * TPB) * 4;

extern "C" void kernel_launch(void* const* d_in, const int* in_sizes, int n_in,
                              void* d_out, int out_size) {
    const float* bf    = (const float*)d_in[0];
    const float* means = (const float*)d_in[1];
    const float* diag  = (const float*)d_in[2];
    const float* fw    = (const float*)d_in[3];
    const float* fb    = (const float*)d_in[4];
    const float* mw    = (const float*)d_in[5];
    const float* mb    = (const float*)d_in[6];
    float* out = (float*)d_out;

    cudaFuncSetAttribute(main_kernel, cudaFuncAttributeMaxDynamicSharedMemorySize, SMEM_BYTES);

    prep_kernel<<<KP, D_>>>(means, diag);
    main_kernel<<<dim3(NPIX / TPB, B_), TPB, SMEM_BYTES>>>(bf, fw, fb, mw, mb, out);
}

// round 4
// speedup vs baseline: 2.1848x; 2.1848x over previous
#include <cuda_runtime.h>
#include <cuda_bf16.h>
#include <math.h>
#include <stdint.h>

#define K_    19
#define P_    5
#define KP    95
#define D_    64
#define NPIX  32768
#define B_    8
#define TPB   256
#define TILEM 256
#define NROW  96          // padded component rows (95 real + 1 zero)
#define RSTRIDE 272       // padded smem/global row stride in bytes (256 data + 16 pad)
#define NT    12          // n-tiles of 8 -> 96 cols
#define KSTEPS 8          // K=128 / 16

// B tables (hi/lo bf16 split), padded-row layout identical to smem image
__device__ __align__(16) unsigned char g_bh[NROW * RSTRIDE];
__device__ __align__(16) unsigned char g_bl[NROW * RSTRIDE];
__device__ float g_cc[96];

// ---------------- helpers ----------------
__device__ __forceinline__ uint32_t smem_u32(const void* p) {
    uint32_t a;
    asm("{ .reg .u64 t; cvta.to.shared.u64 t, %1; cvt.u32.u64 %0, t; }" : "=r"(a) : "l"(p));
    return a;
}
__device__ __forceinline__ uint32_t lds_u32(uint32_t a) {
    uint32_t v;
    asm("ld.shared.b32 %0, [%1];" : "=r"(v) : "r"(a));
    return v;
}
__device__ __forceinline__ uint32_t pkbf(float a, float b) {
    __nv_bfloat162 t = __floats2bfloat162_rn(a, b);   // .x = a (low), .y = b (high)
    return *reinterpret_cast<uint32_t*>(&t);
}

#define MMA_BF16(dp, a0, a1, a2, a3, b0, b1)                                     \
    asm("mma.sync.aligned.m16n8k16.row.col.f32.bf16.bf16.f32 "                   \
        "{%0,%1,%2,%3}, {%4,%5,%6,%7}, {%8,%9}, {%0,%1,%2,%3};"                  \
        : "+f"((dp)[0]), "+f"((dp)[1]), "+f"((dp)[2]), "+f"((dp)[3])             \
        : "r"(a0), "r"(a1), "r"(a2), "r"(a3), "r"(b0), "r"(b1))

// ---------------------------------------------------------------------------
// Prep: l2-normalize means, build hi/lo B images (rows=comp, cols 0..63 = w,
// 64..127 = -0.5*inv_sigma2) and cc constants.  96 blocks x 64 threads.
// ---------------------------------------------------------------------------
__global__ void prep_kernel(const float* __restrict__ means,
                            const float* __restrict__ diag) {
    int j = blockIdx.x;     // 0..95 (row 95 = zero pad)
    int d = threadIdx.x;    // 0..63
    __shared__ float r1[2], r2[2];

    float mu = 0.f, sd = 1.f;
    if (j < KP) { mu = means[j * D_ + d]; sd = diag[j * D_ + d]; }

    float v = mu * mu;
    #pragma unroll
    for (int o = 16; o; o >>= 1) v += __shfl_xor_sync(0xffffffffu, v, o);
    if ((d & 31) == 0) r1[d >> 5] = v;
    __syncthreads();

    float w = 0.f, h = 0.f, cp = 0.f;
    if (j < KP) {
        float nrm = sqrtf(r1[0] + r1[1]);
        float mun = mu / fmaxf(nrm, 1e-12f);
        float i2 = 1.0f / (sd * sd);
        w = mun * i2;
        h = -0.5f * i2;
        cp = -0.5f * mun * mun * i2 - logf(sd);
    }
    float c = cp;
    #pragma unroll
    for (int o = 16; o; o >>= 1) c += __shfl_xor_sync(0xffffffffu, c, o);
    if ((d & 31) == 0) r2[d >> 5] = c;
    __syncthreads();

    if (d == 0)
        g_cc[j] = (j < KP) ? (r2[0] + r2[1] - 32.0f * logf(6.283185307179586f)) : 0.f;

    // write entries (k=d -> w, k=64+d -> h), hi + residual-lo
    {
        __nv_bfloat16 hw = __float2bfloat16(w);
        *(__nv_bfloat16*)(g_bh + j * RSTRIDE + d * 2) = hw;
        *(__nv_bfloat16*)(g_bl + j * RSTRIDE + d * 2) =
            __float2bfloat16(w - __bfloat162float(hw));
        __nv_bfloat16 hh = __float2bfloat16(h);
        *(__nv_bfloat16*)(g_bh + j * RSTRIDE + (64 + d) * 2) = hh;
        *(__nv_bfloat16*)(g_bl + j * RSTRIDE + (64 + d) * 2) =
            __float2bfloat16(h - __bfloat162float(hh));
    }
}

// ---------------------------------------------------------------------------
// smem layout (bytes):
//   A_HI [0,      69632)   256 rows x 272B  (bf16 hi of [x | x^2])
//   A_LO [69632, 139264)   256 rows x 272B  (bf16 residual)
//   B_HI [139264,165376)    96 rows x 272B
//   B_LO [165376,191488)    96 rows x 272B
//   MISC [191488,192544)   cc[96], fw[64], fb[64], mw[19+pad], mb[19]
//   epilogue buffer reuses [0, 99328): 256 rows x 97 floats
// ---------------------------------------------------------------------------
#define A_HI  0
#define A_LO  69632
#define B_HI  139264
#define B_LO  165376
#define MISC  191488
#define SMEM_TOTAL 192544

__global__ void __launch_bounds__(TPB, 1)
main_kernel(const float* __restrict__ bf,
            const float* __restrict__ fw, const float* __restrict__ fb,
            const float* __restrict__ mw, const float* __restrict__ mb,
            float* __restrict__ out) {
    extern __shared__ unsigned char sm[];
    const int tid = threadIdx.x;
    const int wid = tid >> 5;
    const int lane = tid & 31;
    const int g = lane >> 2;        // 0..7
    const int q = lane & 3;         // 0..3

    float* ccs = (float*)(sm + MISC);
    float* fws = (float*)(sm + MISC + 384);
    float* fbs = (float*)(sm + MISC + 640);
    float* mws = (float*)(sm + MISC + 896);
    float* mbs = (float*)(sm + MISC + 976);

    // ---- stage B images + params ----
    {
        const uint4* sbh = (const uint4*)g_bh;
        const uint4* sbl = (const uint4*)g_bl;
        uint4* dbh = (uint4*)(sm + B_HI);
        uint4* dbl = (uint4*)(sm + B_LO);
        for (int i = tid; i < NROW * RSTRIDE / 16; i += TPB) {
            dbh[i] = sbh[i];
            dbl[i] = sbl[i];
        }
    }
    if (tid < 96) ccs[tid] = g_cc[tid];
    if (tid < 64) { fws[tid] = fw[tid]; fbs[tid] = fb[tid]; }
    if (tid < 19) { mws[tid] = mw[tid]; mbs[tid] = mb[tid]; }
    __syncthreads();

    // ---- per-pixel layernorm + l2 ----
    const int n = blockIdx.x * TILEM + tid;
    const int b = blockIdx.y;
    const float* xp = bf + ((size_t)b * D_) * NPIX + n;

    float x[D_];
    #pragma unroll
    for (int d = 0; d < D_; d++) x[d] = xp[(size_t)d * NPIX];

    float s0 = 0.f;
    #pragma unroll
    for (int d = 0; d < D_; d++) s0 += x[d];
    float mean = s0 * (1.0f / D_);
    float vs = 0.f;
    #pragma unroll
    for (int d = 0; d < D_; d++) { x[d] -= mean; vs += x[d] * x[d]; }
    float rstd = rsqrtf(vs * (1.0f / D_) + 1e-5f);
    float ss = 0.f;
    #pragma unroll
    for (int d = 0; d < D_; d++) { float y = x[d] * rstd * fws[d] + fbs[d]; x[d] = y; ss += y * y; }
    float rl = 1.0f / fmaxf(sqrtf(ss), 1e-12f);
    #pragma unroll
    for (int d = 0; d < D_; d++) x[d] *= rl;

    // ---- write A row (hi + lo): 16 chunks of 8 bf16 each ----
    {
        uint4* arH = (uint4*)(sm + A_HI + tid * RSTRIDE);
        uint4* arL = (uint4*)(sm + A_LO + tid * RSTRIDE);
        #pragma unroll
        for (int c = 0; c < 16; c++) {
            uint32_t hv[4], lv[4];
            #pragma unroll
            for (int t = 0; t < 4; t++) {
                float v0, v1;
                if (c < 8) {
                    v0 = x[c * 8 + 2 * t];
                    v1 = x[c * 8 + 2 * t + 1];
                } else {
                    int kk = (c - 8) * 8 + 2 * t;
                    v0 = x[kk] * x[kk];
                    v1 = x[kk + 1] * x[kk + 1];
                }
                __nv_bfloat16 h0 = __float2bfloat16(v0);
                __nv_bfloat16 h1 = __float2bfloat16(v1);
                hv[t] = pkbf(v0, v1);
                lv[t] = pkbf(v0 - __bfloat162float(h0), v1 - __bfloat162float(h1));
            }
            arH[c] = make_uint4(hv[0], hv[1], hv[2], hv[3]);
            arL[c] = make_uint4(lv[0], lv[1], lv[2], lv[3]);
        }
    }
    __syncthreads();

    // ---- GEMM: acc[256x96] += Ah*Bh + Ah*Bl + Al*Bh, f32 accum ----
    float acc[96];
    #pragma unroll
    for (int i = 0; i < 96; i++) acc[i] = 0.f;

    const uint32_t base = smem_u32(sm);
    const int rb = wid * 32;

    uint32_t baseAh[4], baseAl[4], baseBh[NT], baseBl[NT];
    #pragma unroll
    for (int r = 0; r < 4; r++) {
        int row = rb + r * 8 + g;
        baseAh[r] = base + A_HI + row * RSTRIDE + 4 * q;
        baseAl[r] = base + A_LO + row * RSTRIDE + 4 * q;
    }
    #pragma unroll
    for (int j = 0; j < NT; j++) {
        int nr = 8 * j + g;
        baseBh[j] = base + B_HI + nr * RSTRIDE + 4 * q;
        baseBl[j] = base + B_LO + nr * RSTRIDE + 4 * q;
    }

    #pragma unroll
    for (int s = 0; s < KSTEPS; s++) {
        const uint32_t o0 = s * 32;       // k-low chunk byte offset
        const uint32_t o1 = s * 32 + 16;  // k-high chunk

        uint32_t ah[2][4], al[2][4];
        #pragma unroll
        for (int st = 0; st < 2; st++) {
            ah[st][0] = lds_u32(baseAh[2 * st]     + o0);
            ah[st][1] = lds_u32(baseAh[2 * st + 1] + o0);
            ah[st][2] = lds_u32(baseAh[2 * st]     + o1);
            ah[st][3] = lds_u32(baseAh[2 * st + 1] + o1);
            al[st][0] = lds_u32(baseAl[2 * st]     + o0);
            al[st][1] = lds_u32(baseAl[2 * st + 1] + o0);
            al[st][2] = lds_u32(baseAl[2 * st]     + o1);
            al[st][3] = lds_u32(baseAl[2 * st + 1] + o1);
        }

        #pragma unroll
        for (int j = 0; j < NT; j++) {
            uint32_t bh0 = lds_u32(baseBh[j] + o0);
            uint32_t bh1 = lds_u32(baseBh[j] + o1);
            uint32_t bl0 = lds_u32(baseBl[j] + o0);
            uint32_t bl1 = lds_u32(baseBl[j] + o1);
            #pragma unroll
            for (int st = 0; st < 2; st++) {
                float* dp = &acc[(st * NT + j) * 4];
                MMA_BF16(dp, ah[st][0], ah[st][1], ah[st][2], ah[st][3], bh0, bh1);
                MMA_BF16(dp, ah[st][0], ah[st][1], ah[st][2], ah[st][3], bl0, bl1);
                MMA_BF16(dp, al[st][0], al[st][1], al[st][2], al[st][3], bh0, bh1);
            }
        }
    }
    __syncthreads();   // all A reads done; reuse region as epilogue buffer

    // ---- scatter acc to epilogue buffer (row stride 97 floats) ----
    {
        float* epi = (float*)sm;
        #pragma unroll
        for (int st = 0; st < 2; st++) {
            #pragma unroll
            for (int j = 0; j < NT; j++) {
                const float* dp = &acc[(st * NT + j) * 4];
                int r0 = rb + st * 16 + g;
                int col = 8 * j + 2 * q;
                epi[r0 * 97 + col]           = dp[0];
                epi[r0 * 97 + col + 1]       = dp[1];
                epi[(r0 + 8) * 97 + col]     = dp[2];
                epi[(r0 + 8) * 97 + col + 1] = dp[3];
            }
        }
    }
    __syncthreads();

    // ---- per-pixel: +cc, max over 5, LN over 19, transposed store ----
    const float* rp = (const float*)sm + tid * 97;
    float mk[K_];
    {
        int j = 0;
        #pragma unroll
        for (int k = 0; k < K_; k++) {
            float m = -3.4e38f;
            #pragma unroll
            for (int p = 0; p < P_; p++, j++)
                m = fmaxf(m, rp[j] + ccs[j]);
            mk[k] = m;
        }
    }

    float s2 = 0.f;
    #pragma unroll
    for (int k = 0; k < K_; k++) s2 += mk[k];
    float m2 = s2 * (1.0f / K_);
    float v2 = 0.f;
    #pragma unroll
    for (int k = 0; k < K_; k++) { float t = mk[k] - m2; v2 += t * t; }
    float r2 = rsqrtf(v2 * (1.0f / K_) + 1e-5f);

    float* op = out + ((size_t)b * K_) * NPIX + n;
    #pragma unroll
    for (int k = 0; k < K_; k++)
        op[(size_t)k * NPIX] = (mk[k] - m2) * r2 * mws[k] + mbs[k];
}

// ---------------------------------------------------------------------------
extern "C" void kernel_launch(void* const* d_in, const int* in_sizes, int n_in,
                              void* d_out, int out_size) {
    const float* bf    = (const float*)d_in[0];
    const float* means = (const float*)d_in[1];
    const float* diag  = (const float*)d_in[2];
    const float* fw    = (const float*)d_in[3];
    const float* fb    = (const float*)d_in[4];
    const float* mw    = (const float*)d_in[5];
    const float* mb    = (const float*)d_in[6];
    float* out = (float*)d_out;

    cudaFuncSetAttribute(main_kernel, cudaFuncAttributeMaxDynamicSharedMemorySize, SMEM_TOTAL);

    prep_kernel<<<NROW, D_>>>(means, diag);
    main_kernel<<<dim3(NPIX / TILEM, B_), TPB, SMEM_TOTAL>>>(bf, fw, fb, mw, mb, out);
}

// round 5
// speedup vs baseline: 2.1901x; 1.0024x over previous
#include <cuda_runtime.h>
#include <cuda_bf16.h>
#include <math.h>
#include <stdint.h>

#define K_    19
#define P_    5
#define KP    95
#define D_    64
#define NPIX  32768
#define B_    8
#define TPB   256
#define TILEM 256
#define NROW  96          // padded component rows (95 real + 1 zero)
#define RSTRIDE 272       // padded smem row stride in bytes (256 data + 16 pad)
#define NT    12          // n-tiles of 8 -> 96 cols
#define KSTEPS 8          // K=128 / 16

// B tables (hi/lo bf16 split), padded-row layout identical to smem image
__device__ __align__(16) unsigned char g_bh[NROW * RSTRIDE];
__device__ __align__(16) unsigned char g_bl[NROW * RSTRIDE];
__device__ float g_cc[96];

// ---------------- helpers ----------------
__device__ __forceinline__ uint32_t smem_u32(const void* p) {
    uint32_t a;
    asm("{ .reg .u64 t; cvta.to.shared.u64 t, %1; cvt.u32.u64 %0, t; }" : "=r"(a) : "l"(p));
    return a;
}
__device__ __forceinline__ uint32_t lds_u32(uint32_t a) {
    uint32_t v;
    asm("ld.shared.b32 %0, [%1];" : "=r"(v) : "r"(a));
    return v;
}
__device__ __forceinline__ uint32_t pkbf(float a, float b) {
    __nv_bfloat162 t = __floats2bfloat162_rn(a, b);
    return *reinterpret_cast<uint32_t*>(&t);
}

#define MMA_BF16(dp, a0, a1, a2, a3, b0, b1)                                     \
    asm("mma.sync.aligned.m16n8k16.row.col.f32.bf16.bf16.f32 "                   \
        "{%0,%1,%2,%3}, {%4,%5,%6,%7}, {%8,%9}, {%0,%1,%2,%3};"                  \
        : "+f"((dp)[0]), "+f"((dp)[1]), "+f"((dp)[2]), "+f"((dp)[3])             \
        : "r"(a0), "r"(a1), "r"(a2), "r"(a3), "r"(b0), "r"(b1))

// ---------------------------------------------------------------------------
// Prep: l2-normalize means, build hi/lo B images and cc.  96 blocks x 64 thr.
// ---------------------------------------------------------------------------
__global__ void prep_kernel(const float* __restrict__ means,
                            const float* __restrict__ diag) {
    int j = blockIdx.x;     // 0..95 (row 95 = zero pad)
    int d = threadIdx.x;    // 0..63
    __shared__ float r1[2], r2[2];

    float mu = 0.f, sd = 1.f;
    if (j < KP) { mu = means[j * D_ + d]; sd = diag[j * D_ + d]; }

    float v = mu * mu;
    #pragma unroll
    for (int o = 16; o; o >>= 1) v += __shfl_xor_sync(0xffffffffu, v, o);
    if ((d & 31) == 0) r1[d >> 5] = v;
    __syncthreads();

    float w = 0.f, h = 0.f, cp = 0.f;
    if (j < KP) {
        float nrm = sqrtf(r1[0] + r1[1]);
        float mun = mu / fmaxf(nrm, 1e-12f);
        float i2 = 1.0f / (sd * sd);
        w = mun * i2;
        h = -0.5f * i2;
        cp = -0.5f * mun * mun * i2 - logf(sd);
    }
    float c = cp;
    #pragma unroll
    for (int o = 16; o; o >>= 1) c += __shfl_xor_sync(0xffffffffu, c, o);
    if ((d & 31) == 0) r2[d >> 5] = c;
    __syncthreads();

    if (d == 0)
        g_cc[j] = (j < KP) ? (r2[0] + r2[1] - 32.0f * logf(6.283185307179586f)) : 0.f;

    {
        __nv_bfloat16 hw = __float2bfloat16(w);
        *(__nv_bfloat16*)(g_bh + j * RSTRIDE + d * 2) = hw;
        *(__nv_bfloat16*)(g_bl + j * RSTRIDE + d * 2) =
            __float2bfloat16(w - __bfloat162float(hw));
        __nv_bfloat16 hh = __float2bfloat16(h);
        *(__nv_bfloat16*)(g_bh + j * RSTRIDE + (64 + d) * 2) = hh;
        *(__nv_bfloat16*)(g_bl + j * RSTRIDE + (64 + d) * 2) =
            __float2bfloat16(h - __bfloat162float(hh));
    }
}

// ---------------------------------------------------------------------------
// smem layout (bytes)
// ---------------------------------------------------------------------------
#define A_HI  0
#define A_LO  69632
#define B_HI  139264
#define B_LO  165376
#define MISC  191488
#define SMEM_TOTAL 192544

__global__ void __launch_bounds__(TPB, 1)
main_kernel(const float* __restrict__ bf,
            const float* __restrict__ fw, const float* __restrict__ fb,
            const float* __restrict__ mw, const float* __restrict__ mb,
            float* __restrict__ out) {
    extern __shared__ unsigned char sm[];
    const int tid = threadIdx.x;
    const int wid = tid >> 5;
    const int lane = tid & 31;
    const int g = lane >> 2;        // 0..7
    const int q = lane & 3;         // 0..3

    float* ccs = (float*)(sm + MISC);
    float* fws = (float*)(sm + MISC + 384);
    float* fbs = (float*)(sm + MISC + 640);
    float* mws = (float*)(sm + MISC + 896);
    float* mbs = (float*)(sm + MISC + 976);

    // ---- stage B images + params ----
    {
        const uint4* sbh = (const uint4*)g_bh;
        const uint4* sbl = (const uint4*)g_bl;
        uint4* dbh = (uint4*)(sm + B_HI);
        uint4* dbl = (uint4*)(sm + B_LO);
        for (int i = tid; i < NROW * RSTRIDE / 16; i += TPB) {
            dbh[i] = sbh[i];
            dbl[i] = sbl[i];
        }
    }
    if (tid < 96) ccs[tid] = g_cc[tid];
    if (tid < 64) { fws[tid] = fw[tid]; fbs[tid] = fb[tid]; }
    if (tid < 19) { mws[tid] = mw[tid]; mbs[tid] = mb[tid]; }
    __syncthreads();

    // ---- per-pixel layernorm + l2 ----
    const int n = blockIdx.x * TILEM + tid;
    const int b = blockIdx.y;
    const float* xp = bf + ((size_t)b * D_) * NPIX + n;

    float x[D_];
    #pragma unroll
    for (int d = 0; d < D_; d++) x[d] = xp[(size_t)d * NPIX];

    float s0 = 0.f;
    #pragma unroll
    for (int d = 0; d < D_; d++) s0 += x[d];
    float mean = s0 * (1.0f / D_);
    float vs = 0.f;
    #pragma unroll
    for (int d = 0; d < D_; d++) { x[d] -= mean; vs += x[d] * x[d]; }
    float rstd = rsqrtf(vs * (1.0f / D_) + 1e-5f);
    float ss = 0.f;
    #pragma unroll
    for (int d = 0; d < D_; d++) { float y = x[d] * rstd * fws[d] + fbs[d]; x[d] = y; ss += y * y; }
    float rl = 1.0f / fmaxf(sqrtf(ss), 1e-12f);
    #pragma unroll
    for (int d = 0; d < D_; d++) x[d] *= rl;

    // ---- write A row (hi + lo): 16 chunks of 8 bf16 each ----
    {
        uint4* arH = (uint4*)(sm + A_HI + tid * RSTRIDE);
        uint4* arL = (uint4*)(sm + A_LO + tid * RSTRIDE);
        #pragma unroll
        for (int c = 0; c < 16; c++) {
            uint32_t hv[4], lv[4];
            #pragma unroll
            for (int t = 0; t < 4; t++) {
                float v0, v1;
                if (c < 8) {
                    v0 = x[c * 8 + 2 * t];
                    v1 = x[c * 8 + 2 * t + 1];
                } else {
                    int kk = (c - 8) * 8 + 2 * t;
                    v0 = x[kk] * x[kk];
                    v1 = x[kk + 1] * x[kk + 1];
                }
                __nv_bfloat16 h0 = __float2bfloat16(v0);
                __nv_bfloat16 h1 = __float2bfloat16(v1);
                hv[t] = pkbf(v0, v1);
                lv[t] = pkbf(v0 - __bfloat162float(h0), v1 - __bfloat162float(h1));
            }
            arH[c] = make_uint4(hv[0], hv[1], hv[2], hv[3]);
            arL[c] = make_uint4(lv[0], lv[1], lv[2], lv[3]);
        }
    }
    __syncthreads();

    // ---- GEMM: acc[256x96] += Ah*Bh + Al*Bh + Ah*Bl, f32 accum ----
    // Pass-outer ordering: accumulator reuse distance = 24 MMAs (covers HMMA latency)
    float acc[96];
    #pragma unroll
    for (int i = 0; i < 96; i++) acc[i] = 0.f;

    const uint32_t base = smem_u32(sm);
    const int rb = wid * 32;

    // single base regs; everything else folds into LDS immediate offsets
    const uint32_t aH = base + A_HI + (rb + g) * RSTRIDE + 4 * q;
    const uint32_t aL = base + A_LO + (rb + g) * RSTRIDE + 4 * q;
    const uint32_t bH = base + B_HI + g * RSTRIDE + 4 * q;
    const uint32_t bL = base + B_LO + g * RSTRIDE + 4 * q;

    #pragma unroll
    for (int s = 0; s < KSTEPS; s++) {
        const uint32_t o0 = s * 32;       // k-low chunk byte offset
        const uint32_t o1 = s * 32 + 16;  // k-high chunk

        uint32_t ah[2][4], al[2][4];
        #pragma unroll
        for (int st = 0; st < 2; st++) {
            ah[st][0] = lds_u32(aH + (16 * st    ) * RSTRIDE + o0);
            ah[st][1] = lds_u32(aH + (16 * st + 8) * RSTRIDE + o0);
            ah[st][2] = lds_u32(aH + (16 * st    ) * RSTRIDE + o1);
            ah[st][3] = lds_u32(aH + (16 * st + 8) * RSTRIDE + o1);
            al[st][0] = lds_u32(aL + (16 * st    ) * RSTRIDE + o0);
            al[st][1] = lds_u32(aL + (16 * st + 8) * RSTRIDE + o0);
            al[st][2] = lds_u32(aL + (16 * st    ) * RSTRIDE + o1);
            al[st][3] = lds_u32(aL + (16 * st + 8) * RSTRIDE + o1);
        }

        uint32_t bh[NT][2];
        #pragma unroll
        for (int j = 0; j < NT; j++) {
            bh[j][0] = lds_u32(bH + j * 8 * RSTRIDE + o0);
            bh[j][1] = lds_u32(bH + j * 8 * RSTRIDE + o1);
        }

        // pass A: Ah * Bh   (24 MMAs, all-distinct accumulators)
        #pragma unroll
        for (int j = 0; j < NT; j++) {
            MMA_BF16(&acc[j * 4],          ah[0][0], ah[0][1], ah[0][2], ah[0][3], bh[j][0], bh[j][1]);
            MMA_BF16(&acc[(NT + j) * 4],   ah[1][0], ah[1][1], ah[1][2], ah[1][3], bh[j][0], bh[j][1]);
        }

        uint32_t bl[NT][2];
        #pragma unroll
        for (int j = 0; j < NT; j++) {
            bl[j][0] = lds_u32(bL + j * 8 * RSTRIDE + o0);
            bl[j][1] = lds_u32(bL + j * 8 * RSTRIDE + o1);
        }

        // pass B: Al * Bh
        #pragma unroll
        for (int j = 0; j < NT; j++) {
            MMA_BF16(&acc[j * 4],          al[0][0], al[0][1], al[0][2], al[0][3], bh[j][0], bh[j][1]);
            MMA_BF16(&acc[(NT + j) * 4],   al[1][0], al[1][1], al[1][2], al[1][3], bh[j][0], bh[j][1]);
        }

        // pass C: Ah * Bl
        #pragma unroll
        for (int j = 0; j < NT; j++) {
            MMA_BF16(&acc[j * 4],          ah[0][0], ah[0][1], ah[0][2], ah[0][3], bl[j][0], bl[j][1]);
            MMA_BF16(&acc[(NT + j) * 4],   ah[1][0], ah[1][1], ah[1][2], ah[1][3], bl[j][0], bl[j][1]);
        }
    }
    __syncthreads();   // all A reads done; reuse region as epilogue buffer

    // ---- scatter acc to epilogue buffer (row stride 97 floats) ----
    {
        float* epi = (float*)sm;
        #pragma unroll
        for (int st = 0; st < 2; st++) {
            #pragma unroll
            for (int j = 0; j < NT; j++) {
                const float* dp = &acc[(st * NT + j) * 4];
                int r0 = rb + st * 16 + g;
                int col = 8 * j + 2 * q;
                epi[r0 * 97 + col]           = dp[0];
                epi[r0 * 97 + col + 1]       = dp[1];
                epi[(r0 + 8) * 97 + col]     = dp[2];
                epi[(r0 + 8) * 97 + col + 1] = dp[3];
            }
        }
    }
    __syncthreads();

    // ---- per-pixel: +cc, max over 5, LN over 19, transposed store ----
    const float* rp = (const float*)sm + tid * 97;
    float mk[K_];
    {
        int j = 0;
        #pragma unroll
        for (int k = 0; k < K_; k++) {
            float m = -3.4e38f;
            #pragma unroll
            for (int p = 0; p < P_; p++, j++)
                m = fmaxf(m, rp[j] + ccs[j]);
            mk[k] = m;
        }
    }

    float s2 = 0.f;
    #pragma unroll
    for (int k = 0; k < K_; k++) s2 += mk[k];
    float m2 = s2 * (1.0f / K_);
    float v2 = 0.f;
    #pragma unroll
    for (int k = 0; k < K_; k++) { float t = mk[k] - m2; v2 += t * t; }
    float r2 = rsqrtf(v2 * (1.0f / K_) + 1e-5f);

    float* op = out + ((size_t)b * K_) * NPIX + n;
    #pragma unroll
    for (int k = 0; k < K_; k++)
        op[(size_t)k * NPIX] = (mk[k] - m2) * r2 * mws[k] + mbs[k];
}

// ---------------------------------------------------------------------------
extern "C" void kernel_launch(void* const* d_in, const int* in_sizes, int n_in,
                              void* d_out, int out_size) {
    const float* bf    = (const float*)d_in[0];
    const float* means = (const float*)d_in[1];
    const float* diag  = (const float*)d_in[2];
    const float* fw    = (const float*)d_in[3];
    const float* fb    = (const float*)d_in[4];
    const float* mw    = (const float*)d_in[5];
    const float* mb    = (const float*)d_in[6];
    float* out = (float*)d_out;

    cudaFuncSetAttribute(main_kernel, cudaFuncAttributeMaxDynamicSharedMemorySize, SMEM_TOTAL);

    prep_kernel<<<NROW, D_>>>(means, diag);
    main_kernel<<<dim3(NPIX / TILEM, B_), TPB, SMEM_TOTAL>>>(bf, fw, fb, mw, mb, out);
}

// round 6
// speedup vs baseline: 2.2958x; 1.0483x over previous
#include <cuda_runtime.h>
#include <cuda_bf16.h>
#include <math.h>
#include <stdint.h>

#define K_    19
#define P_    5
#define KP    95
#define D_    64
#define NPIX  32768
#define B_    8
#define TPB   128
#define TILEM 128
#define NROW  96          // padded component rows (95 real + 1 zero)
#define RSTRIDE 272       // padded row stride bytes for K=128 images (256 data + 16)
#define LSTRIDE 144       // padded row stride bytes for K=64 A_lo image (128 data + 16)
#define NT    12          // n-tiles of 8 -> 96 cols
#define KSTEPS 8          // K=128 / 16

// B tables (hi/lo bf16 split), padded-row layout identical to smem image
__device__ __align__(16) unsigned char g_bh[NROW * RSTRIDE];
__device__ __align__(16) unsigned char g_bl[NROW * RSTRIDE];
__device__ float g_cc[96];

// ---------------- helpers ----------------
__device__ __forceinline__ uint32_t smem_u32(const void* p) {
    uint32_t a;
    asm("{ .reg .u64 t; cvta.to.shared.u64 t, %1; cvt.u32.u64 %0, t; }" : "=r"(a) : "l"(p));
    return a;
}
__device__ __forceinline__ uint32_t lds_u32(uint32_t a) {
    uint32_t v;
    asm("ld.shared.b32 %0, [%1];" : "=r"(v) : "r"(a));
    return v;
}
__device__ __forceinline__ uint32_t pkbf(float a, float b) {
    __nv_bfloat162 t = __floats2bfloat162_rn(a, b);
    return *reinterpret_cast<uint32_t*>(&t);
}

#define MMA_BF16(dp, a0, a1, a2, a3, b0, b1)                                     \
    asm("mma.sync.aligned.m16n8k16.row.col.f32.bf16.bf16.f32 "                   \
        "{%0,%1,%2,%3}, {%4,%5,%6,%7}, {%8,%9}, {%0,%1,%2,%3};"                  \
        : "+f"((dp)[0]), "+f"((dp)[1]), "+f"((dp)[2]), "+f"((dp)[3])             \
        : "r"(a0), "r"(a1), "r"(a2), "r"(a3), "r"(b0), "r"(b1))

// ---------------------------------------------------------------------------
// Prep: l2-normalize means, build hi/lo B images and cc.  96 blocks x 64 thr.
// ---------------------------------------------------------------------------
__global__ void prep_kernel(const float* __restrict__ means,
                            const float* __restrict__ diag) {
    int j = blockIdx.x;     // 0..95 (row 95 = zero pad)
    int d = threadIdx.x;    // 0..63
    __shared__ float r1[2], r2[2];

    float mu = 0.f, sd = 1.f;
    if (j < KP) { mu = means[j * D_ + d]; sd = diag[j * D_ + d]; }

    float v = mu * mu;
    #pragma unroll
    for (int o = 16; o; o >>= 1) v += __shfl_xor_sync(0xffffffffu, v, o);
    if ((d & 31) == 0) r1[d >> 5] = v;
    __syncthreads();

    float w = 0.f, h = 0.f, cp = 0.f;
    if (j < KP) {
        float nrm = sqrtf(r1[0] + r1[1]);
        float mun = mu / fmaxf(nrm, 1e-12f);
        float i2 = 1.0f / (sd * sd);
        w = mun * i2;
        h = -0.5f * i2;
        cp = -0.5f * mun * mun * i2 - logf(sd);
    }
    float c = cp;
    #pragma unroll
    for (int o = 16; o; o >>= 1) c += __shfl_xor_sync(0xffffffffu, c, o);
    if ((d & 31) == 0) r2[d >> 5] = c;
    __syncthreads();

    if (d == 0)
        g_cc[j] = (j < KP) ? (r2[0] + r2[1] - 32.0f * logf(6.283185307179586f)) : 0.f;

    {
        __nv_bfloat16 hw = __float2bfloat16(w);
        *(__nv_bfloat16*)(g_bh + j * RSTRIDE + d * 2) = hw;
        *(__nv_bfloat16*)(g_bl + j * RSTRIDE + d * 2) =
            __float2bfloat16(w - __bfloat162float(hw));
        __nv_bfloat16 hh = __float2bfloat16(h);
        *(__nv_bfloat16*)(g_bh + j * RSTRIDE + (64 + d) * 2) = hh;
        *(__nv_bfloat16*)(g_bl + j * RSTRIDE + (64 + d) * 2) =
            __float2bfloat16(h - __bfloat162float(hh));
    }
}

// ---------------------------------------------------------------------------
// smem layout (bytes), per CTA (fits 2 CTAs/SM):
//   A_HI [0,      34816)   128 rows x 272B  (bf16 [x | x^2])
//   A_LO [34816,  53248)   128 rows x 144B  (bf16 x-residual, K=64)
//   B_HI [53248,  79360)    96 rows x 272B
//   B_LO [79360, 105472)    96 rows x 272B
//   MISC [105472,106528)   cc[96], fw[64], fb[64], mw, mb
//   epilogue buffer reuses [0, 49664): 128 rows x 97 floats
// ---------------------------------------------------------------------------
#define A_HI  0
#define A_LO  34816
#define B_HI  53248
#define B_LO  79360
#define MISC  105472
#define SMEM_TOTAL 106528

__global__ void __launch_bounds__(TPB, 2)
main_kernel(const float* __restrict__ bf,
            const float* __restrict__ fw, const float* __restrict__ fb,
            const float* __restrict__ mw, const float* __restrict__ mb,
            float* __restrict__ out) {
    extern __shared__ unsigned char sm[];
    const int tid = threadIdx.x;
    const int wid = tid >> 5;
    const int lane = tid & 31;
    const int g = lane >> 2;        // 0..7
    const int q = lane & 3;         // 0..3

    float* ccs = (float*)(sm + MISC);
    float* fws = (float*)(sm + MISC + 384);
    float* fbs = (float*)(sm + MISC + 640);
    float* mws = (float*)(sm + MISC + 896);
    float* mbs = (float*)(sm + MISC + 976);

    // ---- stage B images + params ----
    {
        const uint4* sbh = (const uint4*)g_bh;
        const uint4* sbl = (const uint4*)g_bl;
        uint4* dbh = (uint4*)(sm + B_HI);
        uint4* dbl = (uint4*)(sm + B_LO);
        for (int i = tid; i < NROW * RSTRIDE / 16; i += TPB) {
            dbh[i] = sbh[i];
            dbl[i] = sbl[i];
        }
    }
    if (tid < 96) ccs[tid] = g_cc[tid];
    if (tid < 64) { fws[tid] = fw[tid]; fbs[tid] = fb[tid]; }
    if (tid < 19) { mws[tid] = mw[tid]; mbs[tid] = mb[tid]; }

    // ---- per-pixel layernorm + l2 (loads overlap the staging above) ----
    const int n = blockIdx.x * TILEM + tid;
    const int b = blockIdx.y;
    const float* xp = bf + ((size_t)b * D_) * NPIX + n;

    float x[D_];
    #pragma unroll
    for (int d = 0; d < D_; d++) x[d] = xp[(size_t)d * NPIX];

    __syncthreads();   // staging + param loads visible

    // tree-style reductions (4 accumulators) to shorten latency chains
    float sa0 = 0.f, sa1 = 0.f, sa2 = 0.f, sa3 = 0.f;
    #pragma unroll
    for (int d = 0; d < D_; d += 4) {
        sa0 += x[d]; sa1 += x[d + 1]; sa2 += x[d + 2]; sa3 += x[d + 3];
    }
    float mean = (sa0 + sa1 + sa2 + sa3) * (1.0f / D_);
    float va0 = 0.f, va1 = 0.f, va2 = 0.f, va3 = 0.f;
    #pragma unroll
    for (int d = 0; d < D_; d += 4) {
        float t0 = x[d] - mean, t1 = x[d + 1] - mean, t2 = x[d + 2] - mean, t3 = x[d + 3] - mean;
        x[d] = t0; x[d + 1] = t1; x[d + 2] = t2; x[d + 3] = t3;
        va0 += t0 * t0; va1 += t1 * t1; va2 += t2 * t2; va3 += t3 * t3;
    }
    float rstd = rsqrtf((va0 + va1 + va2 + va3) * (1.0f / D_) + 1e-5f);
    float ea0 = 0.f, ea1 = 0.f, ea2 = 0.f, ea3 = 0.f;
    #pragma unroll
    for (int d = 0; d < D_; d += 4) {
        float y0 = x[d] * rstd * fws[d] + fbs[d];
        float y1 = x[d + 1] * rstd * fws[d + 1] + fbs[d + 1];
        float y2 = x[d + 2] * rstd * fws[d + 2] + fbs[d + 2];
        float y3 = x[d + 3] * rstd * fws[d + 3] + fbs[d + 3];
        x[d] = y0; x[d + 1] = y1; x[d + 2] = y2; x[d + 3] = y3;
        ea0 += y0 * y0; ea1 += y1 * y1; ea2 += y2 * y2; ea3 += y3 * y3;
    }
    float rl = 1.0f / fmaxf(sqrtf(ea0 + ea1 + ea2 + ea3), 1e-12f);
    #pragma unroll
    for (int d = 0; d < D_; d++) x[d] *= rl;

    // ---- write A_hi row: 16 chunks ([x bf16 | x^2 bf16]) ----
    {
        uint4* arH = (uint4*)(sm + A_HI + tid * RSTRIDE);
        #pragma unroll
        for (int c = 0; c < 16; c++) {
            uint32_t hv[4];
            #pragma unroll
            for (int t = 0; t < 4; t++) {
                float v0, v1;
                if (c < 8) {
                    v0 = x[c * 8 + 2 * t];
                    v1 = x[c * 8 + 2 * t + 1];
                } else {
                    int kk = (c - 8) * 8 + 2 * t;
                    v0 = x[kk] * x[kk];
                    v1 = x[kk + 1] * x[kk + 1];
                }
                hv[t] = pkbf(v0, v1);
            }
            arH[c] = make_uint4(hv[0], hv[1], hv[2], hv[3]);
        }
        // A_lo row: x residual only (8 chunks, K=64)
        uint4* arL = (uint4*)(sm + A_LO + tid * LSTRIDE);
        #pragma unroll
        for (int c = 0; c < 8; c++) {
            uint32_t lv[4];
            #pragma unroll
            for (int t = 0; t < 4; t++) {
                float v0 = x[c * 8 + 2 * t];
                float v1 = x[c * 8 + 2 * t + 1];
                lv[t] = pkbf(v0 - __bfloat162float(__float2bfloat16(v0)),
                             v1 - __bfloat162float(__float2bfloat16(v1)));
            }
            arL[c] = make_uint4(lv[0], lv[1], lv[2], lv[3]);
        }
    }
    __syncthreads();

    // ---- GEMM: acc[128x96] = Ah*Bh (K=128) + Al*Bh (K=64) + Ah*Bl (K=128) ----
    float acc[96];
    #pragma unroll
    for (int i = 0; i < 96; i++) acc[i] = 0.f;

    const uint32_t base = smem_u32(sm);
    const int rb = wid * 32;

    const uint32_t aH = base + A_HI + (rb + g) * RSTRIDE + 4 * q;
    const uint32_t aL = base + A_LO + (rb + g) * LSTRIDE + 4 * q;
    const uint32_t bH = base + B_HI + g * RSTRIDE + 4 * q;
    const uint32_t bL = base + B_LO + g * RSTRIDE + 4 * q;

    #pragma unroll
    for (int s = 0; s < KSTEPS; s++) {
        const uint32_t o0 = s * 32;
        const uint32_t o1 = s * 32 + 16;

        uint32_t ah[2][4];
        #pragma unroll
        for (int st = 0; st < 2; st++) {
            ah[st][0] = lds_u32(aH + (16 * st    ) * RSTRIDE + o0);
            ah[st][1] = lds_u32(aH + (16 * st + 8) * RSTRIDE + o0);
            ah[st][2] = lds_u32(aH + (16 * st    ) * RSTRIDE + o1);
            ah[st][3] = lds_u32(aH + (16 * st + 8) * RSTRIDE + o1);
        }
        uint32_t bh[NT][2];
        #pragma unroll
        for (int j = 0; j < NT; j++) {
            bh[j][0] = lds_u32(bH + j * 8 * RSTRIDE + o0);
            bh[j][1] = lds_u32(bH + j * 8 * RSTRIDE + o1);
        }

        // pass A: Ah * Bh
        #pragma unroll
        for (int j = 0; j < NT; j++) {
            MMA_BF16(&acc[j * 4],        ah[0][0], ah[0][1], ah[0][2], ah[0][3], bh[j][0], bh[j][1]);
            MMA_BF16(&acc[(NT + j) * 4], ah[1][0], ah[1][1], ah[1][2], ah[1][3], bh[j][0], bh[j][1]);
        }

        uint32_t bl[NT][2];
        #pragma unroll
        for (int j = 0; j < NT; j++) {
            bl[j][0] = lds_u32(bL + j * 8 * RSTRIDE + o0);
            bl[j][1] = lds_u32(bL + j * 8 * RSTRIDE + o1);
        }

        // pass C: Ah * Bl
        #pragma unroll
        for (int j = 0; j < NT; j++) {
            MMA_BF16(&acc[j * 4],        ah[0][0], ah[0][1], ah[0][2], ah[0][3], bl[j][0], bl[j][1]);
            MMA_BF16(&acc[(NT + j) * 4], ah[1][0], ah[1][1], ah[1][2], ah[1][3], bl[j][0], bl[j][1]);
        }

        // pass B: Al * Bh   (x-residual, K=64 -> first 4 k-steps only)
        if (s < 4) {
            uint32_t al[2][4];
            #pragma unroll
            for (int st = 0; st < 2; st++) {
                al[st][0] = lds_u32(aL + (16 * st    ) * LSTRIDE + o0);
                al[st][1] = lds_u32(aL + (16 * st + 8) * LSTRIDE + o0);
                al[st][2] = lds_u32(aL + (16 * st    ) * LSTRIDE + o1);
                al[st][3] = lds_u32(aL + (16 * st + 8) * LSTRIDE + o1);
            }
            #pragma unroll
            for (int j = 0; j < NT; j++) {
                MMA_BF16(&acc[j * 4],        al[0][0], al[0][1], al[0][2], al[0][3], bh[j][0], bh[j][1]);
                MMA_BF16(&acc[(NT + j) * 4], al[1][0], al[1][1], al[1][2], al[1][3], bh[j][0], bh[j][1]);
            }
        }
    }
    __syncthreads();   // all A reads done; reuse region as epilogue buffer

    // ---- scatter acc to epilogue buffer (row stride 97 floats) ----
    {
        float* epi = (float*)sm;
        #pragma unroll
        for (int st = 0; st < 2; st++) {
            #pragma unroll
            for (int j = 0; j < NT; j++) {
                const float* dp = &acc[(st * NT + j) * 4];
                int r0 = rb + st * 16 + g;
                int col = 8 * j + 2 * q;
                epi[r0 * 97 + col]           = dp[0];
                epi[r0 * 97 + col + 1]       = dp[1];
                epi[(r0 + 8) * 97 + col]     = dp[2];
                epi[(r0 + 8) * 97 + col + 1] = dp[3];
            }
        }
    }
    __syncthreads();

    // ---- per-pixel: +cc, max over 5, LN over 19, transposed store ----
    const float* rp = (const float*)sm + tid * 97;
    float mk[K_];
    {
        int j = 0;
        #pragma unroll
        for (int k = 0; k < K_; k++) {
            float m = -3.4e38f;
            #pragma unroll
            for (int p = 0; p < P_; p++, j++)
                m = fmaxf(m, rp[j] + ccs[j]);
            mk[k] = m;
        }
    }

    float s2 = 0.f;
    #pragma unroll
    for (int k = 0; k < K_; k++) s2 += mk[k];
    float m2 = s2 * (1.0f / K_);
    float v2 = 0.f;
    #pragma unroll
    for (int k = 0; k < K_; k++) { float t = mk[k] - m2; v2 += t * t; }
    float r2 = rsqrtf(v2 * (1.0f / K_) + 1e-5f);

    float* op = out + ((size_t)b * K_) * NPIX + n;
    #pragma unroll
    for (int k = 0; k < K_; k++)
        op[(size_t)k * NPIX] = (mk[k] - m2) * r2 * mws[k] + mbs[k];
}

// ---------------------------------------------------------------------------
extern "C" void kernel_launch(void* const* d_in, const int* in_sizes, int n_in,
                              void* d_out, int out_size) {
    const float* bf    = (const float*)d_in[0];
    const float* means = (const float*)d_in[1];
    const float* diag  = (const float*)d_in[2];
    const float* fw    = (const float*)d_in[3];
    const float* fb    = (const float*)d_in[4];
    const float* mw    = (const float*)d_in[5];
    const float* mb    = (const float*)d_in[6];
    float* out = (float*)d_out;

    cudaFuncSetAttribute(main_kernel, cudaFuncAttributeMaxDynamicSharedMemorySize, SMEM_TOTAL);

    prep_kernel<<<NROW, D_>>>(means, diag);
    main_kernel<<<dim3(NPIX / TILEM, B_), TPB, SMEM_TOTAL>>>(bf, fw, fb, mw, mb, out);
}

// round 7
// speedup vs baseline: 2.7169x; 1.1834x over previous
#include <cuda_runtime.h>
#include <cuda_bf16.h>
#include <math.h>
#include <stdint.h>

#define K_    19
#define P_    5
#define KP    95
#define D_    64
#define NPIX  32768
#define B_    8
#define TPB   256
#define TILEM 128
#define NROW  96          // padded component rows (95 real + 1 zero)
#define RSTRIDE 272       // padded row stride bytes, K=128 images (256 data + 16)
#define LSTRIDE 144       // padded row stride bytes, K=64 A_lo image (128 data + 16)
#define NT    12          // n-tiles of 8 -> 96 cols
#define KSTEPS 8          // K=128 / 16

__device__ __align__(16) unsigned char g_bh[NROW * RSTRIDE];
__device__ __align__(16) unsigned char g_bl[NROW * RSTRIDE];
__device__ float g_cc[96];

// ---------------- helpers ----------------
__device__ __forceinline__ uint32_t smem_u32(const void* p) {
    uint32_t a;
    asm("{ .reg .u64 t; cvta.to.shared.u64 t, %1; cvt.u32.u64 %0, t; }" : "=r"(a) : "l"(p));
    return a;
}
__device__ __forceinline__ uint32_t lds_u32(uint32_t a) {
    uint32_t v;
    asm("ld.shared.b32 %0, [%1];" : "=r"(v) : "r"(a));
    return v;
}
__device__ __forceinline__ uint32_t pkbf(float a, float b) {
    __nv_bfloat162 t = __floats2bfloat162_rn(a, b);
    return *reinterpret_cast<uint32_t*>(&t);
}

#define MMA_BF16(dp, a0, a1, a2, a3, b0, b1)                                     \
    asm("mma.sync.aligned.m16n8k16.row.col.f32.bf16.bf16.f32 "                   \
        "{%0,%1,%2,%3}, {%4,%5,%6,%7}, {%8,%9}, {%0,%1,%2,%3};"                  \
        : "+f"((dp)[0]), "+f"((dp)[1]), "+f"((dp)[2]), "+f"((dp)[3])             \
        : "r"(a0), "r"(a1), "r"(a2), "r"(a3), "r"(b0), "r"(b1))

// ---------------------------------------------------------------------------
// Prep kernel (unchanged)
// ---------------------------------------------------------------------------
__global__ void prep_kernel(const float* __restrict__ means,
                            const float* __restrict__ diag) {
    int j = blockIdx.x;
    int d = threadIdx.x;
    __shared__ float r1[2], r2[2];

    float mu = 0.f, sd = 1.f;
    if (j < KP) { mu = means[j * D_ + d]; sd = diag[j * D_ + d]; }

    float v = mu * mu;
    #pragma unroll
    for (int o = 16; o; o >>= 1) v += __shfl_xor_sync(0xffffffffu, v, o);
    if ((d & 31) == 0) r1[d >> 5] = v;
    __syncthreads();

    float w = 0.f, h = 0.f, cp = 0.f;
    if (j < KP) {
        float nrm = sqrtf(r1[0] + r1[1]);
        float mun = mu / fmaxf(nrm, 1e-12f);
        float i2 = 1.0f / (sd * sd);
        w = mun * i2;
        h = -0.5f * i2;
        cp = -0.5f * mun * mun * i2 - logf(sd);
    }
    float c = cp;
    #pragma unroll
    for (int o = 16; o; o >>= 1) c += __shfl_xor_sync(0xffffffffu, c, o);
    if ((d & 31) == 0) r2[d >> 5] = c;
    __syncthreads();

    if (d == 0)
        g_cc[j] = (j < KP) ? (r2[0] + r2[1] - 32.0f * logf(6.283185307179586f)) : 0.f;

    {
        __nv_bfloat16 hw = __float2bfloat16(w);
        *(__nv_bfloat16*)(g_bh + j * RSTRIDE + d * 2) = hw;
        *(__nv_bfloat16*)(g_bl + j * RSTRIDE + d * 2) =
            __float2bfloat16(w - __bfloat162float(hw));
        __nv_bfloat16 hh = __float2bfloat16(h);
        *(__nv_bfloat16*)(g_bh + j * RSTRIDE + (64 + d) * 2) = hh;
        *(__nv_bfloat16*)(g_bl + j * RSTRIDE + (64 + d) * 2) =
            __float2bfloat16(h - __bfloat162float(hh));
    }
}

// ---------------------------------------------------------------------------
// smem layout (bytes), per CTA (2 CTAs/SM):
//   A_HI [0,      34816)   128 rows x 272B   (LN scratch lives here pre-A)
//   A_LO [34816,  53248)   128 rows x 144B
//   B_HI [53248,  79360)    96 rows x 272B
//   B_LO [79360, 105472)    96 rows x 272B
//   MISC [105472,106528)
//   epilogue buffer reuses [0, 49664): 128 rows x 97 floats
// ---------------------------------------------------------------------------
#define A_HI  0
#define A_LO  34816
#define B_HI  53248
#define B_LO  79360
#define MISC  105472
#define SMEM_TOTAL 106528

__global__ void __launch_bounds__(TPB, 2)
main_kernel(const float* __restrict__ bf,
            const float* __restrict__ fw, const float* __restrict__ fb,
            const float* __restrict__ mw, const float* __restrict__ mb,
            float* __restrict__ out) {
    extern __shared__ unsigned char sm[];
    const int tid = threadIdx.x;
    const int wid = tid >> 5;
    const int lane = tid & 31;
    const int g = lane >> 2;        // 0..7
    const int q = lane & 3;         // 0..3
    const int p = tid & 127;        // pixel within tile
    const int h = tid >> 7;         // d-half (0/1)

    float* ccs = (float*)(sm + MISC);
    float* fws = (float*)(sm + MISC + 384);
    float* fbs = (float*)(sm + MISC + 640);
    float* mws = (float*)(sm + MISC + 896);
    float* mbs = (float*)(sm + MISC + 976);

    // LN cross-half scratch (in A_HI region, free until A rows are written)
    float2* red1 = (float2*)(sm + A_HI);            // [2][128] float2 (2 KB)
    float*  red2 = (float*)(sm + A_HI + 2048);      // [2][128] float  (1 KB)

    // ---- stage B images + params ----
    {
        const uint4* sbh = (const uint4*)g_bh;
        const uint4* sbl = (const uint4*)g_bl;
        uint4* dbh = (uint4*)(sm + B_HI);
        uint4* dbl = (uint4*)(sm + B_LO);
        #pragma unroll
        for (int i = tid; i < NROW * RSTRIDE / 16; i += TPB) {
            dbh[i] = sbh[i];
            dbl[i] = sbl[i];
        }
    }
    if (tid < 96) ccs[tid] = g_cc[tid];
    if (tid < 64) { fws[tid] = fw[tid]; fbs[tid] = fb[tid]; }
    if (tid < 19) { mws[tid] = mw[tid]; mbs[tid] = mb[tid]; }

    // ---- load this thread's 32 dims of its pixel ----
    const int n = blockIdx.x * TILEM + p;
    const int b = blockIdx.y;
    const float* xp = bf + ((size_t)(b * D_ + h * 32)) * NPIX + n;

    float x[32];
    #pragma unroll
    for (int i = 0; i < 32; i++) x[i] = xp[(size_t)i * NPIX];

    // ---- LN round 1: sum & sumsq ----
    float s0 = 0.f, s1 = 0.f, s2 = 0.f, s3 = 0.f;
    float q0 = 0.f, q1 = 0.f, q2 = 0.f, q3 = 0.f;
    #pragma unroll
    for (int i = 0; i < 32; i += 4) {
        s0 += x[i];     q0 += x[i] * x[i];
        s1 += x[i + 1]; q1 += x[i + 1] * x[i + 1];
        s2 += x[i + 2]; q2 += x[i + 2] * x[i + 2];
        s3 += x[i + 3]; q3 += x[i + 3] * x[i + 3];
    }
    red1[h * 128 + p] = make_float2(s0 + s1 + s2 + s3, q0 + q1 + q2 + q3);
    __syncthreads();
    float2 ra = red1[p], rb2 = red1[128 + p];
    float mean = (ra.x + rb2.x) * (1.0f / D_);
    float var = (ra.y + rb2.y) * (1.0f / D_) - mean * mean;
    float rstd = rsqrtf(var + 1e-5f);

    // ---- affine + l2 round ----
    float e0 = 0.f, e1 = 0.f, e2 = 0.f, e3 = 0.f;
    #pragma unroll
    for (int i = 0; i < 32; i += 4) {
        float y0 = (x[i]     - mean) * rstd * fws[h * 32 + i]     + fbs[h * 32 + i];
        float y1 = (x[i + 1] - mean) * rstd * fws[h * 32 + i + 1] + fbs[h * 32 + i + 1];
        float y2 = (x[i + 2] - mean) * rstd * fws[h * 32 + i + 2] + fbs[h * 32 + i + 2];
        float y3 = (x[i + 3] - mean) * rstd * fws[h * 32 + i + 3] + fbs[h * 32 + i + 3];
        x[i] = y0; x[i + 1] = y1; x[i + 2] = y2; x[i + 3] = y3;
        e0 += y0 * y0; e1 += y1 * y1; e2 += y2 * y2; e3 += y3 * y3;
    }
    red2[h * 128 + p] = e0 + e1 + e2 + e3;
    __syncthreads();
    float rl = 1.0f / fmaxf(sqrtf(red2[p] + red2[128 + p]), 1e-12f);
    #pragma unroll
    for (int i = 0; i < 32; i++) x[i] *= rl;
    __syncthreads();   // all scratch reads done; A region now writable

    // ---- write A rows: this thread covers cols [32h,32h+32) and [64+32h, ...) ----
    {
        uint4* arH = (uint4*)(sm + A_HI + p * RSTRIDE + h * 64);           // x part
        uint4* arH2 = (uint4*)(sm + A_HI + p * RSTRIDE + 128 + h * 64);    // x^2 part
        uint4* arL = (uint4*)(sm + A_LO + p * LSTRIDE + h * 64);           // residual
        #pragma unroll
        for (int c = 0; c < 4; c++) {
            uint32_t hv[4], sv[4], lv[4];
            #pragma unroll
            for (int t = 0; t < 4; t++) {
                float v0 = x[c * 8 + 2 * t];
                float v1 = x[c * 8 + 2 * t + 1];
                hv[t] = pkbf(v0, v1);
                sv[t] = pkbf(v0 * v0, v1 * v1);
                lv[t] = pkbf(v0 - __bfloat162float(__float2bfloat16(v0)),
                             v1 - __bfloat162float(__float2bfloat16(v1)));
            }
            arH[c]  = make_uint4(hv[0], hv[1], hv[2], hv[3]);
            arH2[c] = make_uint4(sv[0], sv[1], sv[2], sv[3]);
            arL[c]  = make_uint4(lv[0], lv[1], lv[2], lv[3]);
        }
    }
    __syncthreads();

    // ---- GEMM: 8 warps, each one m16 row-tile; acc[12][4] ----
    float acc[48];
    #pragma unroll
    for (int i = 0; i < 48; i++) acc[i] = 0.f;

    const uint32_t base = smem_u32(sm);
    const int rb = wid * 16;

    const uint32_t aH = base + A_HI + (rb + g) * RSTRIDE + 4 * q;
    const uint32_t aL = base + A_LO + (rb + g) * LSTRIDE + 4 * q;
    const uint32_t bH = base + B_HI + g * RSTRIDE + 4 * q;
    const uint32_t bL = base + B_LO + g * RSTRIDE + 4 * q;

    #pragma unroll
    for (int s = 0; s < KSTEPS; s++) {
        const uint32_t o0 = s * 32;
        const uint32_t o1 = s * 32 + 16;

        uint32_t ah[4];
        ah[0] = lds_u32(aH + o0);
        ah[1] = lds_u32(aH + 8 * RSTRIDE + o0);
        ah[2] = lds_u32(aH + o1);
        ah[3] = lds_u32(aH + 8 * RSTRIDE + o1);

        uint32_t bh[NT][2];
        #pragma unroll
        for (int j = 0; j < NT; j++) {
            bh[j][0] = lds_u32(bH + j * 8 * RSTRIDE + o0);
            bh[j][1] = lds_u32(bH + j * 8 * RSTRIDE + o1);
        }

        // pass A: Ah * Bh
        #pragma unroll
        for (int j = 0; j < NT; j++)
            MMA_BF16(&acc[j * 4], ah[0], ah[1], ah[2], ah[3], bh[j][0], bh[j][1]);

        // pass C: Ah * Bl (loads inline to cap register pressure)
        #pragma unroll
        for (int j = 0; j < NT; j++) {
            uint32_t bl0 = lds_u32(bL + j * 8 * RSTRIDE + o0);
            uint32_t bl1 = lds_u32(bL + j * 8 * RSTRIDE + o1);
            MMA_BF16(&acc[j * 4], ah[0], ah[1], ah[2], ah[3], bl0, bl1);
        }

        // pass B: Al * Bh (x-residual, K=64 -> first 4 k-steps)
        if (s < 4) {
            uint32_t al[4];
            al[0] = lds_u32(aL + o0);
            al[1] = lds_u32(aL + 8 * LSTRIDE + o0);
            al[2] = lds_u32(aL + o1);
            al[3] = lds_u32(aL + 8 * LSTRIDE + o1);
            #pragma unroll
            for (int j = 0; j < NT; j++)
                MMA_BF16(&acc[j * 4], al[0], al[1], al[2], al[3], bh[j][0], bh[j][1]);
        }
    }
    __syncthreads();   // all A/B reads done; reuse region as epilogue buffer

    // ---- scatter acc (row stride 97 floats) ----
    {
        float* epi = (float*)sm;
        #pragma unroll
        for (int j = 0; j < NT; j++) {
            const float* dp = &acc[j * 4];
            int r0 = rb + g;
            int col = 8 * j + 2 * q;
            epi[r0 * 97 + col]           = dp[0];
            epi[r0 * 97 + col + 1]       = dp[1];
            epi[(r0 + 8) * 97 + col]     = dp[2];
            epi[(r0 + 8) * 97 + col + 1] = dp[3];
        }
    }
    __syncthreads();

    // ---- per-pixel epilogue (threads 0..127) ----
    if (tid < 128) {
        const float* rp = (const float*)sm + tid * 97;
        float mk[K_];
        int j = 0;
        #pragma unroll
        for (int k = 0; k < K_; k++) {
            float m = -3.4e38f;
            #pragma unroll
            for (int pp = 0; pp < P_; pp++, j++)
                m = fmaxf(m, rp[j] + ccs[j]);
            mk[k] = m;
        }

        float t0 = 0.f;
        #pragma unroll
        for (int k = 0; k < K_; k++) t0 += mk[k];
        float m2 = t0 * (1.0f / K_);
        float v2 = 0.f;
        #pragma unroll
        for (int k = 0; k < K_; k++) { float t = mk[k] - m2; v2 += t * t; }
        float r2 = rsqrtf(v2 * (1.0f / K_) + 1e-5f);

        float* op = out + ((size_t)b * K_) * NPIX + blockIdx.x * TILEM + tid;
        #pragma unroll
        for (int k = 0; k < K_; k++)
            op[(size_t)k * NPIX] = (mk[k] - m2) * r2 * mws[k] + mbs[k];
    }
}

// ---------------------------------------------------------------------------
extern "C" void kernel_launch(void* const* d_in, const int* in_sizes, int n_in,
                              void* d_out, int out_size) {
    const float* bf    = (const float*)d_in[0];
    const float* means = (const float*)d_in[1];
    const float* diag  = (const float*)d_in[2];
    const float* fw    = (const float*)d_in[3];
    const float* fb    = (const float*)d_in[4];
    const float* mw    = (const float*)d_in[5];
    const float* mb    = (const float*)d_in[6];
    float* out = (float*)d_out;

    cudaFuncSetAttribute(main_kernel, cudaFuncAttributeMaxDynamicSharedMemorySize, SMEM_TOTAL);

    prep_kernel<<<NROW, D_>>>(means, diag);
    main_kernel<<<dim3(NPIX / TILEM, B_), TPB, SMEM_TOTAL>>>(bf, fw, fb, mw, mb, out);
}